// round 16
// baseline (speedup 1.0000x reference)
#include <cuda_runtime.h>
#include <cuda_bf16.h>
#include <stdint.h>
#include <math.h>

#define BT    16384
#define DIN   1024
#define DHID  512
#define DCODE 1024
#define KCB   256
#define T3    3072
#define TSEQ  512
#define NB    32

// ---------------- scratch (device globals; allocations are banned) ----------
__device__ float g_h1[(size_t)BT * DHID];
__device__ float g_feat[(size_t)BT * DCODE];
__device__ float g_q[(size_t)BT * DCODE];
__device__ int   g_idx[BT];
__device__ float g_S[(size_t)BT * KCB];
__device__ float g_cbT[(size_t)DCODE * KCB];
__device__ float g_cnorm[KCB];
__device__ float g_cbWih[(size_t)KCB * T3];   // codebook @ Wih + bih  (3MB)
__device__ float g_pT[(size_t)KCB * DHID];    // relu(codebook @ W1 + b1)
__device__ float g_pm[NB * DHID];
__device__ float g_xm[NB * DCODE];
__device__ float g_recon[(size_t)BT * DIN];
__device__ float g_ctx[(size_t)BT * DCODE];
__device__ float g_hG[2 * NB * DCODE];
__device__ double g_acc[8];   // 0:recon_sse 1:vq_sse 2:xx 3:yy 4:xy
__device__ unsigned g_cnt;
__device__ unsigned g_gen;

// ---------------- f32x2 helpers ----------------------------------------------
__device__ __forceinline__ unsigned long long dup2(float x) {
    unsigned long long r;
    asm("mov.b64 %0, {%1, %1};" : "=l"(r) : "f"(x));
    return r;
}
__device__ __forceinline__ void ffma2(unsigned long long& d,
                                      unsigned long long a, unsigned long long b) {
    asm("fma.rn.f32x2 %0, %1, %2, %0;" : "+l"(d) : "l"(a), "l"(b));
}
__device__ __forceinline__ void unpk(unsigned long long v, float& lo, float& hi) {
    asm("mov.b64 {%0, %1}, %2;" : "=f"(lo), "=f"(hi) : "l"(v));
}

// ---------------- block reduce (256 threads) -> atomicAdd double ------------
__device__ __forceinline__ void block_reduce_add(double local, double* dst) {
    __shared__ double sred[8];
    int tid = threadIdx.x;
    #pragma unroll
    for (int o = 16; o; o >>= 1)
        local += __shfl_down_sync(0xffffffffu, local, o);
    if ((tid & 31) == 0) sred[tid >> 5] = local;
    __syncthreads();
    if (tid == 0) {
        double s = 0.0;
        #pragma unroll
        for (int i = 0; i < 8; i++) s += sred[i];
        atomicAdd(dst, s);
    }
}

// ---------------- generic MSE-sum: sum((a-b)^2) -> g_acc[slot] --------------
__global__ void __launch_bounds__(256) mse_kernel(const float* __restrict__ a,
                                                  const float* __restrict__ b,
                                                  size_t n, int slot) {
    double local = 0.0;
    size_t i = (size_t)blockIdx.x * blockDim.x + threadIdx.x;
    size_t stride = (size_t)gridDim.x * blockDim.x;
    for (; i < n; i += stride) {
        double d = (double)a[i] - (double)b[i];
        local += d * d;
    }
    block_reduce_add(local, &g_acc[slot]);
}

// ---------------- bf16 HMMA GEMM (identical to R6 best) ---------------------
#define LDA 40
#define LDB 136

__device__ __forceinline__ uint32_t pack_bf16(float lo, float hi) {
    __nv_bfloat162 v = __floats2bfloat162_rn(lo, hi);
    return *reinterpret_cast<uint32_t*>(&v);
}

__device__ __forceinline__ void mma16816(float* c, const uint32_t* a, const uint32_t* b) {
    asm volatile(
        "mma.sync.aligned.m16n8k16.row.col.f32.bf16.bf16.f32 "
        "{%0,%1,%2,%3}, {%4,%5,%6,%7}, {%8,%9}, {%0,%1,%2,%3};"
        : "+f"(c[0]), "+f"(c[1]), "+f"(c[2]), "+f"(c[3])
        : "r"(a[0]), "r"(a[1]), "r"(a[2]), "r"(a[3]), "r"(b[0]), "r"(b[1]));
}

__device__ __forceinline__ void ldsm_x4(uint32_t* r, uint32_t addr) {
    asm volatile("ldmatrix.sync.aligned.m8n8.x4.shared.b16 {%0,%1,%2,%3}, [%4];"
                 : "=r"(r[0]), "=r"(r[1]), "=r"(r[2]), "=r"(r[3]) : "r"(addr));
}
__device__ __forceinline__ void ldsm_x4_t(uint32_t* r, uint32_t addr) {
    asm volatile("ldmatrix.sync.aligned.m8n8.x4.trans.shared.b16 {%0,%1,%2,%3}, [%4];"
                 : "=r"(r[0]), "=r"(r[1]), "=r"(r[2]), "=r"(r[3]) : "r"(addr));
}

template <int EPI>
__global__ void __launch_bounds__(256, 2) hgemm(
    const float* __restrict__ A, const float* __restrict__ B,
    const float* __restrict__ bias, float* __restrict__ C,
    int M, int N, int K)
{
    __shared__ __nv_bfloat16 As[2][128 * LDA];
    __shared__ __nv_bfloat16 Bs[2][32 * LDB];

    const int tid = threadIdx.x;
    const int wid = tid >> 5, lane = tid & 31;
    const int g = lane >> 2, tg = lane & 3;
    const int wm = wid >> 2, wn = wid & 3;
    const int bx = blockIdx.x, by = blockIdx.y;

    float acc[4][4][4];
    #pragma unroll
    for (int i = 0; i < 4; i++)
        #pragma unroll
        for (int j = 0; j < 4; j++)
            #pragma unroll
            for (int e = 0; e < 4; e++) acc[i][j][e] = 0.f;

    const int arow = tid >> 3;
    const int acol = (tid & 7) << 2;
    const int brow = tid >> 5;
    const int bcol = (tid & 31) << 2;

    const float* Ag = A + (size_t)(by * 128 + arow) * K + acol;
    const float* Bg = B + (size_t)brow * N + bx * 128 + bcol;

    const int a_r = wm * 64 + (lane & 15);
    const int a_c = (lane >> 4) << 3;
    const int grp = lane >> 3;
    const int b_r = ((grp & 1) << 3) + (lane & 7);
    const int b_c = wn * 32 + ((grp >> 1) << 3);

    uint32_t As_sh = (uint32_t)__cvta_generic_to_shared(&As[0][0]);
    uint32_t Bs_sh = (uint32_t)__cvta_generic_to_shared(&Bs[0][0]);

    float4 stA[4], stB[4];

    #pragma unroll
    for (int p = 0; p < 4; p++) stA[p] = *(const float4*)(Ag + (size_t)(p * 32) * K);
    #pragma unroll
    for (int p = 0; p < 4; p++) stB[p] = *(const float4*)(Bg + (size_t)(p * 8) * N);
    #pragma unroll
    for (int p = 0; p < 4; p++) {
        uint2 u = make_uint2(pack_bf16(stA[p].x, stA[p].y), pack_bf16(stA[p].z, stA[p].w));
        *reinterpret_cast<uint2*>(&As[0][(arow + p * 32) * LDA + acol]) = u;
    }
    #pragma unroll
    for (int p = 0; p < 4; p++) {
        uint2 u = make_uint2(pack_bf16(stB[p].x, stB[p].y), pack_bf16(stB[p].z, stB[p].w));
        *reinterpret_cast<uint2*>(&Bs[0][(brow + p * 8) * LDB + bcol]) = u;
    }
    __syncthreads();

    int cur = 0;
    for (int k0 = 0; k0 < K; k0 += 32) {
        const bool more = (k0 + 32) < K;
        if (more) {
            #pragma unroll
            for (int p = 0; p < 4; p++)
                stA[p] = *(const float4*)(Ag + (size_t)(p * 32) * K + (k0 + 32));
            #pragma unroll
            for (int p = 0; p < 4; p++)
                stB[p] = *(const float4*)(Bg + (size_t)(k0 + 32 + p * 8) * N);
        }

        const uint32_t Abase = As_sh + (uint32_t)(cur * 128 * LDA * 2);
        const uint32_t Bbase = Bs_sh + (uint32_t)(cur * 32 * LDB * 2);

        #pragma unroll
        for (int kk = 0; kk < 32; kk += 16) {
            uint32_t af[4][4];
            #pragma unroll
            for (int im = 0; im < 4; im++)
                ldsm_x4(af[im], Abase + (uint32_t)(((a_r + im * 16) * LDA + a_c + kk) * 2));
            uint32_t bf[4][4];
            #pragma unroll
            for (int jp = 0; jp < 2; jp++) {
                uint32_t r[4];
                ldsm_x4_t(r, Bbase + (uint32_t)(((b_r + kk) * LDB + b_c + jp * 16) * 2));
                bf[2 * jp][0] = r[0]; bf[2 * jp][1] = r[1];
                bf[2 * jp + 1][0] = r[2]; bf[2 * jp + 1][1] = r[3];
            }
            #pragma unroll
            for (int im = 0; im < 4; im++)
                #pragma unroll
                for (int jn = 0; jn < 4; jn++)
                    mma16816(acc[im][jn], af[im], bf[jn]);
        }

        if (more) {
            const int nxt = cur ^ 1;
            #pragma unroll
            for (int p = 0; p < 4; p++) {
                uint2 u = make_uint2(pack_bf16(stA[p].x, stA[p].y), pack_bf16(stA[p].z, stA[p].w));
                *reinterpret_cast<uint2*>(&As[nxt][(arow + p * 32) * LDA + acol]) = u;
            }
            #pragma unroll
            for (int p = 0; p < 4; p++) {
                uint2 u = make_uint2(pack_bf16(stB[p].x, stB[p].y), pack_bf16(stB[p].z, stB[p].w));
                *reinterpret_cast<uint2*>(&Bs[nxt][(brow + p * 8) * LDB + bcol]) = u;
            }
            __syncthreads();
            cur = nxt;
        }
    }

    #pragma unroll
    for (int im = 0; im < 4; im++) {
        int r0 = by * 128 + wm * 64 + im * 16 + g;
        #pragma unroll
        for (int jn = 0; jn < 4; jn++) {
            int c0 = bx * 128 + wn * 32 + jn * 8 + tg * 2;
            float b0 = bias ? bias[c0] : 0.f;
            float b1 = bias ? bias[c0 + 1] : 0.f;
            float v0 = acc[im][jn][0] + b0;
            float v1 = acc[im][jn][1] + b1;
            float v2 = acc[im][jn][2] + b0;
            float v3 = acc[im][jn][3] + b1;
            if (EPI == 1) {
                v0 = fmaxf(v0, 0.f); v1 = fmaxf(v1, 0.f);
                v2 = fmaxf(v2, 0.f); v3 = fmaxf(v3, 0.f);
            }
            *(float2*)&C[(size_t)r0 * N + c0] = make_float2(v0, v1);
            *(float2*)&C[(size_t)(r0 + 8) * N + c0] = make_float2(v2, v3);
        }
    }
}

// ---------------- LayerNorm(512) + ReLU in place ----------------------------
__global__ void __launch_bounds__(256) ln_relu(float* __restrict__ h,
                                               const float* __restrict__ gg,
                                               const float* __restrict__ bb)
{
    __shared__ float red[16];
    int tid = threadIdx.x;
    float* r = h + (size_t)blockIdx.x * DHID;
    float v0 = r[tid], v1 = r[tid + 256];
    float s = v0 + v1, q = v0 * v0 + v1 * v1;
    #pragma unroll
    for (int o = 16; o; o >>= 1) {
        s += __shfl_xor_sync(0xffffffffu, s, o);
        q += __shfl_xor_sync(0xffffffffu, q, o);
    }
    if ((tid & 31) == 0) { red[tid >> 5] = s; red[8 + (tid >> 5)] = q; }
    __syncthreads();
    if (tid < 32) {
        float ss = (tid < 8) ? red[tid] : 0.f;
        float qq = (tid < 8) ? red[8 + tid] : 0.f;
        #pragma unroll
        for (int o = 4; o; o >>= 1) {
            ss += __shfl_xor_sync(0xffffffffu, ss, o);
            qq += __shfl_xor_sync(0xffffffffu, qq, o);
        }
        if (tid == 0) { red[0] = ss; red[1] = qq; }
    }
    __syncthreads();
    float mean = red[0] * (1.f / 512.f);
    float var = red[1] * (1.f / 512.f) - mean * mean;
    float rs = rsqrtf(var + 1e-5f);
    r[tid]       = fmaxf((v0 - mean) * rs * gg[tid] + bb[tid], 0.f);
    r[tid + 256] = fmaxf((v1 - mean) * rs * gg[tid + 256] + bb[tid + 256], 0.f);
}

// ---------------- VQ helpers (R13 proven path: materialize g_q) --------------
__global__ void transpose_cb(const float* __restrict__ cb) {
    int d = blockIdx.x, k = threadIdx.x;
    g_cbT[(size_t)d * KCB + k] = cb[(size_t)k * DCODE + d];
}

__global__ void __launch_bounds__(256) cnorm_k(const float* __restrict__ cb) {
    __shared__ float red[8];
    int k = blockIdx.x, tid = threadIdx.x;
    const float* row = cb + (size_t)k * DCODE;
    float s = 0.f;
    for (int d = tid; d < DCODE; d += 256) { float v = row[d]; s += v * v; }
    #pragma unroll
    for (int o = 16; o; o >>= 1) s += __shfl_xor_sync(0xffffffffu, s, o);
    if ((tid & 31) == 0) red[tid >> 5] = s;
    __syncthreads();
    if (tid == 0) {
        float t = 0.f;
        #pragma unroll
        for (int i = 0; i < 8; i++) t += red[i];
        g_cnorm[k] = t;
    }
}

__global__ void __launch_bounds__(256) vq_kernel(const float* __restrict__ cb) {
    __shared__ float sv[256];
    __shared__ int si[256];
    int tok = blockIdx.x, tid = threadIdx.x;
    float v = g_cnorm[tid] - 2.f * g_S[(size_t)tok * KCB + tid];
    sv[tid] = v; si[tid] = tid;
    __syncthreads();
    for (int s = 128; s > 0; s >>= 1) {
        if (tid < s) {
            float v2 = sv[tid + s]; int i2 = si[tid + s];
            if (v2 < sv[tid] || (v2 == sv[tid] && i2 < si[tid])) { sv[tid] = v2; si[tid] = i2; }
        }
        __syncthreads();
    }
    int best = si[0];
    if (tid == 0) g_idx[tok] = best;
    const float* crow = cb + (size_t)best * DCODE;
    float* qrow = g_q + (size_t)tok * DCODE;
    #pragma unroll
    for (int i = 0; i < 4; i++) {
        int d = tid + i * 256;
        qrow[d] = crow[d];
    }
}

// ---------------- pm via gather-mean over pTable ------------------------------
__global__ void __launch_bounds__(256) pm_gather() {
    int b = blockIdx.x, d = threadIdx.x;
    const int* ib = g_idx + b * TSEQ;
    float a0 = 0.f, a1 = 0.f;
    for (int t = 0; t < TSEQ; t++) {
        int k = ib[t];
        const float* row = g_pT + (size_t)k * DHID;
        a0 += row[d];
        a1 += row[d + 256];
    }
    g_pm[b * DHID + d]       = a0 * (1.f / (float)TSEQ);
    g_pm[b * DHID + d + 256] = a1 * (1.f / (float)TSEQ);
}

__global__ void __launch_bounds__(256) xm_kernel(const float* __restrict__ W2,
                                                 const float* __restrict__ b2) {
    __shared__ float sp[DHID];
    int b = blockIdx.x;
    int n = blockIdx.y * 256 + threadIdx.x;
    for (int e = threadIdx.x; e < DHID; e += 256) sp[e] = g_pm[b * DHID + e];
    __syncthreads();
    float a = b2[n];
    for (int k = 0; k < DHID; k++) a += sp[k] * W2[(size_t)k * DCODE + n];
    g_xm[b * DCODE + n] = a;
}

__global__ void __launch_bounds__(256) mmd_kernel(const float* __restrict__ prior) {
    int i = blockIdx.x;
    int m = blockIdx.y;
    const float* Arow = ((m == 1) ? prior : g_xm) + (size_t)i * DCODE;
    const float* Bmat = (m == 0) ? g_xm : prior;
    int j = threadIdx.x >> 3, part = threadIdx.x & 7;
    const float* Brow = Bmat + (size_t)j * DCODE;
    float s = 0.f;
    for (int d = part; d < DCODE; d += 8) { float df = Arow[d] - Brow[d]; s += df * df; }
    s += __shfl_xor_sync(0xffffffffu, s, 1);
    s += __shfl_xor_sync(0xffffffffu, s, 2);
    s += __shfl_xor_sync(0xffffffffu, s, 4);
    if (part == 0) atomicAdd(&g_acc[2 + m], exp(-(double)s / 1024.0));
}

// ---------------- persistent GRU scan (f32x2 j-pairs, R13 barrier) -----------
// 128 blocks x 128 threads; thread = (jp 0..3, b 0..31); warp == one jp
// (Wp shared loads are 32-lane broadcasts). Per-j arithmetic matches R13.
__device__ __forceinline__ void grid_bar() {
    __threadfence();
    __syncthreads();
    if (threadIdx.x == 0) {
        unsigned g = atomicAdd(&g_gen, 0u);
        if (atomicAdd(&g_cnt, 1u) == gridDim.x - 1) {
            atomicExch(&g_cnt, 0u);
            atomicAdd(&g_gen, 1u);
        } else {
            while (atomicAdd(&g_gen, 0u) == g) { __nanosleep(64); }
        }
    }
    __syncthreads();
    __threadfence();
}

#define GRU_SMEM ((24 * 1024 + NB * DCODE) * (int)sizeof(float))

__global__ void __launch_bounds__(128, 1) gru_scan(
    const float* __restrict__ Whh, const float* __restrict__ bhh)
{
    extern __shared__ float sm[];
    float2* Wp = (float2*)sm;       // 12*1024 float2 (96KB): [gate*4+jp][k]
    float* hT = sm + 24 * 1024;     // 32768 floats [k][b] (128KB)

    const int tid = threadIdx.x;
    const int jp = tid >> 5;
    const int b = tid & 31;
    const int j0 = blockIdx.x * 8;
    const int jg = j0 + 2 * jp;

    for (int e = tid; e < 12 * 1024; e += 128) {
        int c = e >> 10, k = e & 1023;
        int gate = c >> 2, jpp = c & 3;
        int col = gate * DCODE + j0 + 2 * jpp;
        Wp[c * 1024 + k] = *(const float2*)&Whh[(size_t)k * T3 + col];
    }
    for (int e = tid * 4; e < NB * DCODE; e += 512)
        *(float4*)(hT + e) = make_float4(0.f, 0.f, 0.f, 0.f);
    __syncthreads();

    const float2* wr = Wp + (0 * 4 + jp) * 1024;
    const float2* wz = Wp + (1 * 4 + jp) * 1024;
    const float2* wn = Wp + (2 * 4 + jp) * 1024;
    const float2 brv = *(const float2*)&bhh[0 * DCODE + jg];
    const float2 bzv = *(const float2*)&bhh[1 * DCODE + jg];
    const float2 bnv = *(const float2*)&bhh[2 * DCODE + jg];
    const float* hb = hT + b;
    const int* ib = g_idx + b * TSEQ;

    for (int t = 0; t < TSEQ; t++) {
        if (t > 0) {
            grid_bar();
            const float* src = g_hG + (size_t)((t - 1) & 1) * (NB * DCODE);
            for (int e = tid * 4; e < NB * DCODE; e += 512) {
                float4 v = __ldcg((const float4*)(src + e));
                *(float4*)(hT + e) = v;
            }
            __syncthreads();
        }
        int kq = ib[t];
        unsigned long long ar = 0ull, az = 0ull, an = 0ull;
        #pragma unroll 4
        for (int k = 0; k < 1024; k += 2) {
            unsigned long long hh0 = dup2(hb[k * 32]);
            unsigned long long hh1 = dup2(hb[k * 32 + 32]);
            ulonglong2 w0 = *(const ulonglong2*)&wr[k];
            ffma2(ar, hh0, w0.x); ffma2(ar, hh1, w0.y);
            ulonglong2 w1 = *(const ulonglong2*)&wz[k];
            ffma2(az, hh0, w1.x); ffma2(az, hh1, w1.y);
            ulonglong2 w2 = *(const ulonglong2*)&wn[k];
            ffma2(an, hh0, w2.x); ffma2(an, hh1, w2.y);
        }
        const float* gxp = g_cbWih + (size_t)kq * T3;
        float2 xr = *(const float2*)&gxp[jg];
        float2 xz = *(const float2*)&gxp[DCODE + jg];
        float2 xn = *(const float2*)&gxp[2 * DCODE + jg];
        float ar0, ar1, az0, az1, an0, an1;
        unpk(ar, ar0, ar1); unpk(az, az0, az1); unpk(an, an0, an1);
        float r0 = 1.f / (1.f + expf(-(xr.x + ar0 + brv.x)));
        float r1 = 1.f / (1.f + expf(-(xr.y + ar1 + brv.y)));
        float z0 = 1.f / (1.f + expf(-(xz.x + az0 + bzv.x)));
        float z1 = 1.f / (1.f + expf(-(xz.y + az1 + bzv.y)));
        float n0 = tanhf(xn.x + r0 * (an0 + bnv.x));
        float n1 = tanhf(xn.y + r1 * (an1 + bnv.y));
        float hp0 = hT[jg * 32 + b];
        float hp1 = hT[(jg + 1) * 32 + b];
        float hn0 = (1.f - z0) * n0 + z0 * hp0;
        float hn1 = (1.f - z1) * n1 + z1 * hp1;
        *(float2*)&g_ctx[((size_t)b * TSEQ + t) * DCODE + jg] = make_float2(hn0, hn1);
        float* dst = g_hG + (size_t)(t & 1) * (NB * DCODE);
        __stcg(&dst[jg * 32 + b], hn0);
        __stcg(&dst[(jg + 1) * 32 + b], hn1);
    }
}

// ---------------- init / finalize -------------------------------------------
__global__ void zero_acc() {
    if (threadIdx.x < 8) g_acc[threadIdx.x] = 0.0;
    if (threadIdx.x == 0) { g_cnt = 0u; g_gen = 0u; }
}

__global__ void finalize(float* __restrict__ out) {
    double recon = g_acc[0] / ((double)BT * (double)DIN);
    double vq    = 1.25 * g_acc[1] / ((double)BT * (double)DCODE);
    double xx = g_acc[2] / 1024.0, yy = g_acc[3] / 1024.0, xy = g_acc[4] / 1024.0;
    double mmd = xx + yy - 2.0 * xy;
    out[0] = (float)recon;
    out[1] = (float)vq;
    out[2] = (float)mmd;
    out[3] = (float)(recon + vq + 0.5 * mmd);
}

// ---------------- launch -----------------------------------------------------
extern "C" void kernel_launch(void* const* d_in, const int* in_sizes, int n_in,
                              void* d_out, int out_size) {
    const float* x       = (const float*)d_in[0];
    const float* prior   = (const float*)d_in[1];
    const float* enc_W1  = (const float*)d_in[2];
    const float* enc_b1  = (const float*)d_in[3];
    const float* ln_g    = (const float*)d_in[4];
    const float* ln_b    = (const float*)d_in[5];
    const float* enc_W2  = (const float*)d_in[6];
    const float* enc_b2  = (const float*)d_in[7];
    const float* codebook= (const float*)d_in[8];
    const float* proj_W1 = (const float*)d_in[9];
    const float* proj_b1 = (const float*)d_in[10];
    const float* proj_W2 = (const float*)d_in[11];
    const float* proj_b2 = (const float*)d_in[12];
    const float* gru_Wih = (const float*)d_in[13];
    const float* gru_Whh = (const float*)d_in[14];
    const float* gru_bih = (const float*)d_in[15];
    const float* gru_bhh = (const float*)d_in[16];
    const float* head_W  = (const float*)d_in[17];
    const float* head_b  = (const float*)d_in[18];
    float* out = (float*)d_out;

    cudaFuncSetAttribute(gru_scan, cudaFuncAttributeMaxDynamicSharedMemorySize, GRU_SMEM);

    zero_acc<<<1, 32>>>();

    // encoder
    hgemm<0><<<dim3(DHID / 128, BT / 128), 256>>>(x, enc_W1, enc_b1, g_h1,
                                                  BT, DHID, DIN);
    ln_relu<<<BT, 256>>>(g_h1, ln_g, ln_b);
    hgemm<0><<<dim3(DCODE / 128, BT / 128), 256>>>(g_h1, enc_W2, enc_b2, g_feat,
                                                   BT, DCODE, DHID);
    // VQ (R13 proven path)
    transpose_cb<<<DCODE, KCB>>>(codebook);
    cnorm_k<<<KCB, 256>>>(codebook);
    hgemm<0><<<dim3(KCB / 128, BT / 128), 256>>>(g_feat, g_cbT, nullptr, g_S,
                                                 BT, KCB, DCODE);
    vq_kernel<<<BT, 256>>>(codebook);
    mse_kernel<<<1024, 256>>>(g_q, g_feat, (size_t)BT * DCODE, 1);

    // codebook tables (256 rows)
    hgemm<0><<<dim3(T3 / 128, KCB / 128), 256>>>(codebook, gru_Wih, gru_bih, g_cbWih,
                                                 KCB, T3, DCODE);
    hgemm<1><<<dim3(DHID / 128, KCB / 128), 256>>>(codebook, proj_W1, proj_b1, g_pT,
                                                   KCB, DHID, DCODE);

    // projector mean via gather + MMD
    pm_gather<<<NB, 256>>>();
    xm_kernel<<<dim3(NB, DCODE / 256), 256>>>(proj_W2, proj_b2);
    mmd_kernel<<<dim3(NB, 3), 256>>>(prior);

    // GRU scan (f32x2 j-pairs; gx from L2-resident cbWih table)
    gru_scan<<<128, 128, GRU_SMEM>>>(gru_Whh, gru_bhh);

    // head + decoupled recon loss
    hgemm<0><<<dim3(DIN / 128, BT / 128), 256>>>(g_ctx, head_W, head_b, g_recon,
                                                 BT, DIN, DCODE);
    mse_kernel<<<1024, 256>>>(g_recon, x, (size_t)BT * DIN, 0);

    finalize<<<1, 1>>>(out);
}

// round 17
// speedup vs baseline: 1.0969x; 1.0969x over previous
#include <cuda_runtime.h>
#include <cuda_bf16.h>
#include <stdint.h>
#include <math.h>

#define BT    16384
#define DIN   1024
#define DHID  512
#define DCODE 1024
#define KCB   256
#define T3    3072
#define TSEQ  512
#define NB    32

// ---------------- scratch (device globals; allocations are banned) ----------
__device__ float g_h1[(size_t)BT * DHID];
__device__ float g_feat[(size_t)BT * DCODE];
__device__ float g_q[(size_t)BT * DCODE];
__device__ int   g_idx[BT];
__device__ float g_S[(size_t)BT * KCB];
__device__ float g_cbT[(size_t)DCODE * KCB];
__device__ float g_cnorm[KCB];
__device__ float g_cbWih[(size_t)KCB * T3];   // codebook @ Wih + bih  (3MB)
__device__ float g_pT[(size_t)KCB * DHID];    // relu(codebook @ W1 + b1)
__device__ float g_pm[NB * DHID];
__device__ float g_xm[NB * DCODE];
__device__ float g_recon[(size_t)BT * DIN];
__device__ float g_ctx[(size_t)BT * DCODE];
__device__ float g_hG[2 * NB * DCODE];
__device__ double g_acc[8];   // 0:recon_sse 1:vq_sse 2:xx 3:yy 4:xy
__device__ unsigned g_cnt;
__device__ unsigned g_gen;

// ---------------- f32x2 helpers ----------------------------------------------
__device__ __forceinline__ unsigned long long dup2(float x) {
    unsigned long long r;
    asm("mov.b64 %0, {%1, %1};" : "=l"(r) : "f"(x));
    return r;
}
__device__ __forceinline__ void ffma2(unsigned long long& d,
                                      unsigned long long a, unsigned long long b) {
    asm("fma.rn.f32x2 %0, %1, %2, %0;" : "+l"(d) : "l"(a), "l"(b));
}
__device__ __forceinline__ unsigned long long addf2(unsigned long long a,
                                                    unsigned long long b) {
    unsigned long long r;
    asm("add.rn.f32x2 %0, %1, %2;" : "=l"(r) : "l"(a), "l"(b));
    return r;
}
__device__ __forceinline__ void unpk(unsigned long long v, float& lo, float& hi) {
    asm("mov.b64 {%0, %1}, %2;" : "=f"(lo), "=f"(hi) : "l"(v));
}

// ---------------- block reduce (256 threads) -> atomicAdd double ------------
__device__ __forceinline__ void block_reduce_add(double local, double* dst) {
    __shared__ double sred[8];
    int tid = threadIdx.x;
    #pragma unroll
    for (int o = 16; o; o >>= 1)
        local += __shfl_down_sync(0xffffffffu, local, o);
    if ((tid & 31) == 0) sred[tid >> 5] = local;
    __syncthreads();
    if (tid == 0) {
        double s = 0.0;
        #pragma unroll
        for (int i = 0; i < 8; i++) s += sred[i];
        atomicAdd(dst, s);
    }
}

// ---------------- generic MSE-sum: sum((a-b)^2) -> g_acc[slot] --------------
__global__ void __launch_bounds__(256) mse_kernel(const float* __restrict__ a,
                                                  const float* __restrict__ b,
                                                  size_t n, int slot) {
    double local = 0.0;
    size_t i = (size_t)blockIdx.x * blockDim.x + threadIdx.x;
    size_t stride = (size_t)gridDim.x * blockDim.x;
    for (; i < n; i += stride) {
        double d = (double)a[i] - (double)b[i];
        local += d * d;
    }
    block_reduce_add(local, &g_acc[slot]);
}

// ---------------- bf16 HMMA GEMM (identical to R6 best) ---------------------
#define LDA 40
#define LDB 136

__device__ __forceinline__ uint32_t pack_bf16(float lo, float hi) {
    __nv_bfloat162 v = __floats2bfloat162_rn(lo, hi);
    return *reinterpret_cast<uint32_t*>(&v);
}

__device__ __forceinline__ void mma16816(float* c, const uint32_t* a, const uint32_t* b) {
    asm volatile(
        "mma.sync.aligned.m16n8k16.row.col.f32.bf16.bf16.f32 "
        "{%0,%1,%2,%3}, {%4,%5,%6,%7}, {%8,%9}, {%0,%1,%2,%3};"
        : "+f"(c[0]), "+f"(c[1]), "+f"(c[2]), "+f"(c[3])
        : "r"(a[0]), "r"(a[1]), "r"(a[2]), "r"(a[3]), "r"(b[0]), "r"(b[1]));
}

__device__ __forceinline__ void ldsm_x4(uint32_t* r, uint32_t addr) {
    asm volatile("ldmatrix.sync.aligned.m8n8.x4.shared.b16 {%0,%1,%2,%3}, [%4];"
                 : "=r"(r[0]), "=r"(r[1]), "=r"(r[2]), "=r"(r[3]) : "r"(addr));
}
__device__ __forceinline__ void ldsm_x4_t(uint32_t* r, uint32_t addr) {
    asm volatile("ldmatrix.sync.aligned.m8n8.x4.trans.shared.b16 {%0,%1,%2,%3}, [%4];"
                 : "=r"(r[0]), "=r"(r[1]), "=r"(r[2]), "=r"(r[3]) : "r"(addr));
}

template <int EPI>
__global__ void __launch_bounds__(256, 2) hgemm(
    const float* __restrict__ A, const float* __restrict__ B,
    const float* __restrict__ bias, float* __restrict__ C,
    int M, int N, int K)
{
    __shared__ __nv_bfloat16 As[2][128 * LDA];
    __shared__ __nv_bfloat16 Bs[2][32 * LDB];

    const int tid = threadIdx.x;
    const int wid = tid >> 5, lane = tid & 31;
    const int g = lane >> 2, tg = lane & 3;
    const int wm = wid >> 2, wn = wid & 3;
    const int bx = blockIdx.x, by = blockIdx.y;

    float acc[4][4][4];
    #pragma unroll
    for (int i = 0; i < 4; i++)
        #pragma unroll
        for (int j = 0; j < 4; j++)
            #pragma unroll
            for (int e = 0; e < 4; e++) acc[i][j][e] = 0.f;

    const int arow = tid >> 3;
    const int acol = (tid & 7) << 2;
    const int brow = tid >> 5;
    const int bcol = (tid & 31) << 2;

    const float* Ag = A + (size_t)(by * 128 + arow) * K + acol;
    const float* Bg = B + (size_t)brow * N + bx * 128 + bcol;

    const int a_r = wm * 64 + (lane & 15);
    const int a_c = (lane >> 4) << 3;
    const int grp = lane >> 3;
    const int b_r = ((grp & 1) << 3) + (lane & 7);
    const int b_c = wn * 32 + ((grp >> 1) << 3);

    uint32_t As_sh = (uint32_t)__cvta_generic_to_shared(&As[0][0]);
    uint32_t Bs_sh = (uint32_t)__cvta_generic_to_shared(&Bs[0][0]);

    float4 stA[4], stB[4];

    #pragma unroll
    for (int p = 0; p < 4; p++) stA[p] = *(const float4*)(Ag + (size_t)(p * 32) * K);
    #pragma unroll
    for (int p = 0; p < 4; p++) stB[p] = *(const float4*)(Bg + (size_t)(p * 8) * N);
    #pragma unroll
    for (int p = 0; p < 4; p++) {
        uint2 u = make_uint2(pack_bf16(stA[p].x, stA[p].y), pack_bf16(stA[p].z, stA[p].w));
        *reinterpret_cast<uint2*>(&As[0][(arow + p * 32) * LDA + acol]) = u;
    }
    #pragma unroll
    for (int p = 0; p < 4; p++) {
        uint2 u = make_uint2(pack_bf16(stB[p].x, stB[p].y), pack_bf16(stB[p].z, stB[p].w));
        *reinterpret_cast<uint2*>(&Bs[0][(brow + p * 8) * LDB + bcol]) = u;
    }
    __syncthreads();

    int cur = 0;
    for (int k0 = 0; k0 < K; k0 += 32) {
        const bool more = (k0 + 32) < K;
        if (more) {
            #pragma unroll
            for (int p = 0; p < 4; p++)
                stA[p] = *(const float4*)(Ag + (size_t)(p * 32) * K + (k0 + 32));
            #pragma unroll
            for (int p = 0; p < 4; p++)
                stB[p] = *(const float4*)(Bg + (size_t)(k0 + 32 + p * 8) * N);
        }

        const uint32_t Abase = As_sh + (uint32_t)(cur * 128 * LDA * 2);
        const uint32_t Bbase = Bs_sh + (uint32_t)(cur * 32 * LDB * 2);

        #pragma unroll
        for (int kk = 0; kk < 32; kk += 16) {
            uint32_t af[4][4];
            #pragma unroll
            for (int im = 0; im < 4; im++)
                ldsm_x4(af[im], Abase + (uint32_t)(((a_r + im * 16) * LDA + a_c + kk) * 2));
            uint32_t bf[4][4];
            #pragma unroll
            for (int jp = 0; jp < 2; jp++) {
                uint32_t r[4];
                ldsm_x4_t(r, Bbase + (uint32_t)(((b_r + kk) * LDB + b_c + jp * 16) * 2));
                bf[2 * jp][0] = r[0]; bf[2 * jp][1] = r[1];
                bf[2 * jp + 1][0] = r[2]; bf[2 * jp + 1][1] = r[3];
            }
            #pragma unroll
            for (int im = 0; im < 4; im++)
                #pragma unroll
                for (int jn = 0; jn < 4; jn++)
                    mma16816(acc[im][jn], af[im], bf[jn]);
        }

        if (more) {
            const int nxt = cur ^ 1;
            #pragma unroll
            for (int p = 0; p < 4; p++) {
                uint2 u = make_uint2(pack_bf16(stA[p].x, stA[p].y), pack_bf16(stA[p].z, stA[p].w));
                *reinterpret_cast<uint2*>(&As[nxt][(arow + p * 32) * LDA + acol]) = u;
            }
            #pragma unroll
            for (int p = 0; p < 4; p++) {
                uint2 u = make_uint2(pack_bf16(stB[p].x, stB[p].y), pack_bf16(stB[p].z, stB[p].w));
                *reinterpret_cast<uint2*>(&Bs[nxt][(brow + p * 8) * LDB + bcol]) = u;
            }
            __syncthreads();
            cur = nxt;
        }
    }

    #pragma unroll
    for (int im = 0; im < 4; im++) {
        int r0 = by * 128 + wm * 64 + im * 16 + g;
        #pragma unroll
        for (int jn = 0; jn < 4; jn++) {
            int c0 = bx * 128 + wn * 32 + jn * 8 + tg * 2;
            float b0 = bias ? bias[c0] : 0.f;
            float b1 = bias ? bias[c0 + 1] : 0.f;
            float v0 = acc[im][jn][0] + b0;
            float v1 = acc[im][jn][1] + b1;
            float v2 = acc[im][jn][2] + b0;
            float v3 = acc[im][jn][3] + b1;
            if (EPI == 1) {
                v0 = fmaxf(v0, 0.f); v1 = fmaxf(v1, 0.f);
                v2 = fmaxf(v2, 0.f); v3 = fmaxf(v3, 0.f);
            }
            *(float2*)&C[(size_t)r0 * N + c0] = make_float2(v0, v1);
            *(float2*)&C[(size_t)(r0 + 8) * N + c0] = make_float2(v2, v3);
        }
    }
}

// ---------------- LayerNorm(512) + ReLU in place ----------------------------
__global__ void __launch_bounds__(256) ln_relu(float* __restrict__ h,
                                               const float* __restrict__ gg,
                                               const float* __restrict__ bb)
{
    __shared__ float red[16];
    int tid = threadIdx.x;
    float* r = h + (size_t)blockIdx.x * DHID;
    float v0 = r[tid], v1 = r[tid + 256];
    float s = v0 + v1, q = v0 * v0 + v1 * v1;
    #pragma unroll
    for (int o = 16; o; o >>= 1) {
        s += __shfl_xor_sync(0xffffffffu, s, o);
        q += __shfl_xor_sync(0xffffffffu, q, o);
    }
    if ((tid & 31) == 0) { red[tid >> 5] = s; red[8 + (tid >> 5)] = q; }
    __syncthreads();
    if (tid < 32) {
        float ss = (tid < 8) ? red[tid] : 0.f;
        float qq = (tid < 8) ? red[8 + tid] : 0.f;
        #pragma unroll
        for (int o = 4; o; o >>= 1) {
            ss += __shfl_xor_sync(0xffffffffu, ss, o);
            qq += __shfl_xor_sync(0xffffffffu, qq, o);
        }
        if (tid == 0) { red[0] = ss; red[1] = qq; }
    }
    __syncthreads();
    float mean = red[0] * (1.f / 512.f);
    float var = red[1] * (1.f / 512.f) - mean * mean;
    float rs = rsqrtf(var + 1e-5f);
    r[tid]       = fmaxf((v0 - mean) * rs * gg[tid] + bb[tid], 0.f);
    r[tid + 256] = fmaxf((v1 - mean) * rs * gg[tid + 256] + bb[tid + 256], 0.f);
}

// ---------------- VQ helpers (R13 proven path: materialize g_q) --------------
__global__ void transpose_cb(const float* __restrict__ cb) {
    int d = blockIdx.x, k = threadIdx.x;
    g_cbT[(size_t)d * KCB + k] = cb[(size_t)k * DCODE + d];
}

__global__ void __launch_bounds__(256) cnorm_k(const float* __restrict__ cb) {
    __shared__ float red[8];
    int k = blockIdx.x, tid = threadIdx.x;
    const float* row = cb + (size_t)k * DCODE;
    float s = 0.f;
    for (int d = tid; d < DCODE; d += 256) { float v = row[d]; s += v * v; }
    #pragma unroll
    for (int o = 16; o; o >>= 1) s += __shfl_xor_sync(0xffffffffu, s, o);
    if ((tid & 31) == 0) red[tid >> 5] = s;
    __syncthreads();
    if (tid == 0) {
        float t = 0.f;
        #pragma unroll
        for (int i = 0; i < 8; i++) t += red[i];
        g_cnorm[k] = t;
    }
}

__global__ void __launch_bounds__(256) vq_kernel(const float* __restrict__ cb) {
    __shared__ float sv[256];
    __shared__ int si[256];
    int tok = blockIdx.x, tid = threadIdx.x;
    float v = g_cnorm[tid] - 2.f * g_S[(size_t)tok * KCB + tid];
    sv[tid] = v; si[tid] = tid;
    __syncthreads();
    for (int s = 128; s > 0; s >>= 1) {
        if (tid < s) {
            float v2 = sv[tid + s]; int i2 = si[tid + s];
            if (v2 < sv[tid] || (v2 == sv[tid] && i2 < si[tid])) { sv[tid] = v2; si[tid] = i2; }
        }
        __syncthreads();
    }
    int best = si[0];
    if (tid == 0) g_idx[tok] = best;
    const float* crow = cb + (size_t)best * DCODE;
    float* qrow = g_q + (size_t)tok * DCODE;
    #pragma unroll
    for (int i = 0; i < 4; i++) {
        int d = tid + i * 256;
        qrow[d] = crow[d];
    }
}

// ---------------- pm via gather-mean over pTable ------------------------------
__global__ void __launch_bounds__(256) pm_gather() {
    int b = blockIdx.x, d = threadIdx.x;
    const int* ib = g_idx + b * TSEQ;
    float a0 = 0.f, a1 = 0.f;
    for (int t = 0; t < TSEQ; t++) {
        int k = ib[t];
        const float* row = g_pT + (size_t)k * DHID;
        a0 += row[d];
        a1 += row[d + 256];
    }
    g_pm[b * DHID + d]       = a0 * (1.f / (float)TSEQ);
    g_pm[b * DHID + d + 256] = a1 * (1.f / (float)TSEQ);
}

__global__ void __launch_bounds__(256) xm_kernel(const float* __restrict__ W2,
                                                 const float* __restrict__ b2) {
    __shared__ float sp[DHID];
    int b = blockIdx.x;
    int n = blockIdx.y * 256 + threadIdx.x;
    for (int e = threadIdx.x; e < DHID; e += 256) sp[e] = g_pm[b * DHID + e];
    __syncthreads();
    float a = b2[n];
    for (int k = 0; k < DHID; k++) a += sp[k] * W2[(size_t)k * DCODE + n];
    g_xm[b * DCODE + n] = a;
}

__global__ void __launch_bounds__(256) mmd_kernel(const float* __restrict__ prior) {
    int i = blockIdx.x;
    int m = blockIdx.y;
    const float* Arow = ((m == 1) ? prior : g_xm) + (size_t)i * DCODE;
    const float* Bmat = (m == 0) ? g_xm : prior;
    int j = threadIdx.x >> 3, part = threadIdx.x & 7;
    const float* Brow = Bmat + (size_t)j * DCODE;
    float s = 0.f;
    for (int d = part; d < DCODE; d += 8) { float df = Arow[d] - Brow[d]; s += df * df; }
    s += __shfl_xor_sync(0xffffffffu, s, 1);
    s += __shfl_xor_sync(0xffffffffu, s, 2);
    s += __shfl_xor_sync(0xffffffffu, s, 4);
    if (part == 0) atomicAdd(&g_acc[2 + m], exp(-(double)s / 1024.0));
}

// ---------------- persistent GRU scan (f32x2 j-pairs + 2 k-teams, 256 thr) ---
// 128 blocks x 256 threads; thread = (team tid>>7, jp (tid>>5)&3, b tid&31).
// 2 warps/SMSP (latency hiding restored) with halved FFMA work per thread.
// R13's exact barrier and hT fill; math per j matches R13 modulo k-split order.
__device__ __forceinline__ void grid_bar() {
    __threadfence();
    __syncthreads();
    if (threadIdx.x == 0) {
        unsigned g = atomicAdd(&g_gen, 0u);
        if (atomicAdd(&g_cnt, 1u) == gridDim.x - 1) {
            atomicExch(&g_cnt, 0u);
            atomicAdd(&g_gen, 1u);
        } else {
            while (atomicAdd(&g_gen, 0u) == g) { __nanosleep(64); }
        }
    }
    __syncthreads();
    __threadfence();
}

#define GRU_SMEM ((24 * 1024 + NB * DCODE) * (int)sizeof(float))   // 229376 B dyn

__global__ void __launch_bounds__(256, 1) gru_scan(
    const float* __restrict__ Whh, const float* __restrict__ bhh)
{
    extern __shared__ float sm[];
    float2* Wp = (float2*)sm;       // 12*1024 float2 (96KB): [gate*4+jp][k]
    float* hT = sm + 24 * 1024;     // 32768 floats [k][b] (128KB)
    __shared__ unsigned long long part[384];   // 3KB static

    const int tid = threadIdx.x;
    const int team = tid >> 7;
    const int jp = (tid >> 5) & 3;
    const int b = tid & 31;
    const int j0 = blockIdx.x * 8;
    const int jg = j0 + 2 * jp;
    const int kbase = team * 512;

    for (int e = tid; e < 12 * 1024; e += 256) {
        int c = e >> 10, k = e & 1023;
        int gate = c >> 2, jpp = c & 3;
        int col = gate * DCODE + j0 + 2 * jpp;
        Wp[c * 1024 + k] = *(const float2*)&Whh[(size_t)k * T3 + col];
    }
    for (int e = tid * 4; e < NB * DCODE; e += 1024)
        *(float4*)(hT + e) = make_float4(0.f, 0.f, 0.f, 0.f);
    __syncthreads();

    const float2* wr = Wp + (0 * 4 + jp) * 1024 + kbase;
    const float2* wz = Wp + (1 * 4 + jp) * 1024 + kbase;
    const float2* wn = Wp + (2 * 4 + jp) * 1024 + kbase;
    const float2 brv = *(const float2*)&bhh[0 * DCODE + jg];
    const float2 bzv = *(const float2*)&bhh[1 * DCODE + jg];
    const float2 bnv = *(const float2*)&bhh[2 * DCODE + jg];
    const float* hk = hT + kbase * 32 + b;
    const int* ib = g_idx + b * TSEQ;

    for (int t = 0; t < TSEQ; t++) {
        if (t > 0) {
            grid_bar();
            const float* src = g_hG + (size_t)((t - 1) & 1) * (NB * DCODE);
            for (int e = tid * 4; e < NB * DCODE; e += 1024) {
                float4 v = __ldcg((const float4*)(src + e));
                *(float4*)(hT + e) = v;
            }
            __syncthreads();
        }
        int kq = ib[t];
        unsigned long long ar = 0ull, az = 0ull, an = 0ull;
        #pragma unroll 4
        for (int k = 0; k < 512; k += 2) {
            unsigned long long hh0 = dup2(hk[k * 32]);
            unsigned long long hh1 = dup2(hk[k * 32 + 32]);
            ulonglong2 w0 = *(const ulonglong2*)&wr[k];
            ffma2(ar, hh0, w0.x); ffma2(ar, hh1, w0.y);
            ulonglong2 w1 = *(const ulonglong2*)&wz[k];
            ffma2(az, hh0, w1.x); ffma2(az, hh1, w1.y);
            ulonglong2 w2 = *(const ulonglong2*)&wn[k];
            ffma2(an, hh0, w2.x); ffma2(an, hh1, w2.y);
        }
        if (team == 1) {
            part[(0 * 4 + jp) * 32 + b] = ar;
            part[(1 * 4 + jp) * 32 + b] = az;
            part[(2 * 4 + jp) * 32 + b] = an;
        }
        __syncthreads();
        if (team == 0) {
            ar = addf2(ar, part[(0 * 4 + jp) * 32 + b]);
            az = addf2(az, part[(1 * 4 + jp) * 32 + b]);
            an = addf2(an, part[(2 * 4 + jp) * 32 + b]);
            const float* gxp = g_cbWih + (size_t)kq * T3;
            float2 xr = *(const float2*)&gxp[jg];
            float2 xz = *(const float2*)&gxp[DCODE + jg];
            float2 xn = *(const float2*)&gxp[2 * DCODE + jg];
            float ar0, ar1, az0, az1, an0, an1;
            unpk(ar, ar0, ar1); unpk(az, az0, az1); unpk(an, an0, an1);
            float r0 = 1.f / (1.f + expf(-(xr.x + ar0 + brv.x)));
            float r1 = 1.f / (1.f + expf(-(xr.y + ar1 + brv.y)));
            float z0 = 1.f / (1.f + expf(-(xz.x + az0 + bzv.x)));
            float z1 = 1.f / (1.f + expf(-(xz.y + az1 + bzv.y)));
            float n0 = tanhf(xn.x + r0 * (an0 + bnv.x));
            float n1 = tanhf(xn.y + r1 * (an1 + bnv.y));
            float hp0 = hT[jg * 32 + b];
            float hp1 = hT[(jg + 1) * 32 + b];
            float hn0 = (1.f - z0) * n0 + z0 * hp0;
            float hn1 = (1.f - z1) * n1 + z1 * hp1;
            *(float2*)&g_ctx[((size_t)b * TSEQ + t) * DCODE + jg] = make_float2(hn0, hn1);
            float* dst = g_hG + (size_t)(t & 1) * (NB * DCODE);
            __stcg(&dst[jg * 32 + b], hn0);
            __stcg(&dst[(jg + 1) * 32 + b], hn1);
        }
    }
}

// ---------------- init / finalize -------------------------------------------
__global__ void zero_acc() {
    if (threadIdx.x < 8) g_acc[threadIdx.x] = 0.0;
    if (threadIdx.x == 0) { g_cnt = 0u; g_gen = 0u; }
}

__global__ void finalize(float* __restrict__ out) {
    double recon = g_acc[0] / ((double)BT * (double)DIN);
    double vq    = 1.25 * g_acc[1] / ((double)BT * (double)DCODE);
    double xx = g_acc[2] / 1024.0, yy = g_acc[3] / 1024.0, xy = g_acc[4] / 1024.0;
    double mmd = xx + yy - 2.0 * xy;
    out[0] = (float)recon;
    out[1] = (float)vq;
    out[2] = (float)mmd;
    out[3] = (float)(recon + vq + 0.5 * mmd);
}

// ---------------- launch -----------------------------------------------------
extern "C" void kernel_launch(void* const* d_in, const int* in_sizes, int n_in,
                              void* d_out, int out_size) {
    const float* x       = (const float*)d_in[0];
    const float* prior   = (const float*)d_in[1];
    const float* enc_W1  = (const float*)d_in[2];
    const float* enc_b1  = (const float*)d_in[3];
    const float* ln_g    = (const float*)d_in[4];
    const float* ln_b    = (const float*)d_in[5];
    const float* enc_W2  = (const float*)d_in[6];
    const float* enc_b2  = (const float*)d_in[7];
    const float* codebook= (const float*)d_in[8];
    const float* proj_W1 = (const float*)d_in[9];
    const float* proj_b1 = (const float*)d_in[10];
    const float* proj_W2 = (const float*)d_in[11];
    const float* proj_b2 = (const float*)d_in[12];
    const float* gru_Wih = (const float*)d_in[13];
    const float* gru_Whh = (const float*)d_in[14];
    const float* gru_bih = (const float*)d_in[15];
    const float* gru_bhh = (const float*)d_in[16];
    const float* head_W  = (const float*)d_in[17];
    const float* head_b  = (const float*)d_in[18];
    float* out = (float*)d_out;

    cudaFuncSetAttribute(gru_scan, cudaFuncAttributeMaxDynamicSharedMemorySize, GRU_SMEM);

    zero_acc<<<1, 32>>>();

    // encoder
    hgemm<0><<<dim3(DHID / 128, BT / 128), 256>>>(x, enc_W1, enc_b1, g_h1,
                                                  BT, DHID, DIN);
    ln_relu<<<BT, 256>>>(g_h1, ln_g, ln_b);
    hgemm<0><<<dim3(DCODE / 128, BT / 128), 256>>>(g_h1, enc_W2, enc_b2, g_feat,
                                                   BT, DCODE, DHID);
    // VQ (R13 proven path)
    transpose_cb<<<DCODE, KCB>>>(codebook);
    cnorm_k<<<KCB, 256>>>(codebook);
    hgemm<0><<<dim3(KCB / 128, BT / 128), 256>>>(g_feat, g_cbT, nullptr, g_S,
                                                 BT, KCB, DCODE);
    vq_kernel<<<BT, 256>>>(codebook);
    mse_kernel<<<1024, 256>>>(g_q, g_feat, (size_t)BT * DCODE, 1);

    // codebook tables (256 rows)
    hgemm<0><<<dim3(T3 / 128, KCB / 128), 256>>>(codebook, gru_Wih, gru_bih, g_cbWih,
                                                 KCB, T3, DCODE);
    hgemm<1><<<dim3(DHID / 128, KCB / 128), 256>>>(codebook, proj_W1, proj_b1, g_pT,
                                                   KCB, DHID, DCODE);

    // projector mean via gather + MMD
    pm_gather<<<NB, 256>>>();
    xm_kernel<<<dim3(NB, DCODE / 256), 256>>>(proj_W2, proj_b2);
    mmd_kernel<<<dim3(NB, 3), 256>>>(prior);

    // GRU scan (f32x2 j-pairs, 2 k-teams; gx from L2-resident cbWih table)
    gru_scan<<<128, 256, GRU_SMEM>>>(gru_Whh, gru_bhh);

    // head + decoupled recon loss
    hgemm<0><<<dim3(DIN / 128, BT / 128), 256>>>(g_ctx, head_W, head_b, g_recon,
                                                 BT, DIN, DCODE);
    mse_kernel<<<1024, 256>>>(g_recon, x, (size_t)BT * DIN, 0);

    finalize<<<1, 1>>>(out);
}